// round 9
// baseline (speedup 1.0000x reference)
#include <cuda_runtime.h>
#include <cstdint>
#include <math.h>

// Problem dims
#define T_SEQ 512
#define BATCH 8
#define HID   512
#define EMB   256
#define VOCAB 32000
#define M_TOT (BATCH*T_SEQ)   // 4096
#define G4H   (4*HID)         // 2048

// ---------------- scratch (device globals; no allocation allowed) -----------
__device__ float g_x0 [M_TOT*EMB];      // gathered embeddings
__device__ float g_xg [M_TOT*G4H];      // layer0 input-gate contributions
__device__ float g_hs1[M_TOT*HID];      // layer1 outputs (FC input)
__device__ float g_h0 [2][HID*BATCH];   // double-buffered h, layout [n][b]
__device__ float g_h1 [2][HID*BATCH];
__device__ float g_c  [2][HID*BATCH];   // cell state per layer, layout [n][b]

// ---------------- embedding gather ------------------------------------------
__global__ void gather_kernel(const int* __restrict__ ids,
                              const float* __restrict__ emb) {
    int m  = blockIdx.x;
    int id = ids[m];
    const float4* s = (const float4*)(emb + (size_t)id * EMB);
    float4*       d = (float4*)(g_x0 + (size_t)m * EMB);
    d[threadIdx.x] = s[threadIdx.x];
}

// ---------------- state reset (before the recurrence) -----------------------
__global__ void reset_kernel() {
    int i = blockIdx.x * blockDim.x + threadIdx.x;
    int n = HID * BATCH;
    if (i < n) {
        g_h0[0][i] = 0.f; g_h0[1][i] = 0.f;
        g_h1[0][i] = 0.f; g_h1[1][i] = 0.f;
        g_c [0][i] = 0.f; g_c [1][i] = 0.f;
    }
}

// ---------------- tf32 mma GEMM: C[m][n] = sum_k A[m][k]*B[n][k] + bias -----
// A row-major [M][K], B row-major [N][K]; M%128==0, N%128==0, K%32==0
__device__ __forceinline__ float f2tf32(float x) {
    float r;
    asm("cvt.rna.tf32.f32 %0, %1;" : "=f"(r) : "f"(x));
    return r;
}

__global__ void __launch_bounds__(256)
gemm_tf32_kernel(const float* __restrict__ A, const float* __restrict__ B,
                 const float* __restrict__ bias1, const float* __restrict__ bias2,
                 float* __restrict__ C, int M, int N, int K)
{
    __shared__ float As[128][36];
    __shared__ float Bs[128][36];

    int tid  = threadIdx.x;
    int warp = tid >> 5, lane = tid & 31;
    int wm   = warp >> 2, wn = warp & 3;          // 2 x 4 warp grid
    int grp  = lane >> 2, tig = lane & 3;

    int mBase = blockIdx.y << 7;
    int nBase = blockIdx.x << 7;

    float acc[4][4][4];
    #pragma unroll
    for (int a = 0; a < 4; a++)
        #pragma unroll
        for (int b = 0; b < 4; b++)
            #pragma unroll
            for (int c = 0; c < 4; c++) acc[a][b][c] = 0.f;

    for (int k0 = 0; k0 < K; k0 += 32) {
        #pragma unroll
        for (int i = 0; i < 4; i++) {
            int f  = tid + (i << 8);              // 0..1023 float4 slots
            int m  = f >> 3;
            int k4 = (f & 7) << 2;
            float4 va = *(const float4*)(A + (size_t)(mBase + m) * K + k0 + k4);
            *(float4*)&As[m][k4] = make_float4(f2tf32(va.x), f2tf32(va.y),
                                               f2tf32(va.z), f2tf32(va.w));
            float4 vb = *(const float4*)(B + (size_t)(nBase + m) * K + k0 + k4);
            *(float4*)&Bs[m][k4] = make_float4(f2tf32(vb.x), f2tf32(vb.y),
                                               f2tf32(vb.z), f2tf32(vb.w));
        }
        __syncthreads();

        #pragma unroll
        for (int kk = 0; kk < 32; kk += 8) {
            uint32_t af[4][4], bf[4][2];
            #pragma unroll
            for (int mi = 0; mi < 4; mi++) {
                int r = (wm << 6) + (mi << 4);
                af[mi][0] = __float_as_uint(As[r + grp    ][kk + tig    ]);
                af[mi][1] = __float_as_uint(As[r + grp + 8][kk + tig    ]);
                af[mi][2] = __float_as_uint(As[r + grp    ][kk + tig + 4]);
                af[mi][3] = __float_as_uint(As[r + grp + 8][kk + tig + 4]);
            }
            #pragma unroll
            for (int ni = 0; ni < 4; ni++) {
                int cN = (wn << 5) + (ni << 3);
                bf[ni][0] = __float_as_uint(Bs[cN + grp][kk + tig    ]);
                bf[ni][1] = __float_as_uint(Bs[cN + grp][kk + tig + 4]);
            }
            #pragma unroll
            for (int mi = 0; mi < 4; mi++)
                #pragma unroll
                for (int ni = 0; ni < 4; ni++)
                    asm volatile(
                        "mma.sync.aligned.m16n8k8.row.col.f32.tf32.tf32.f32 "
                        "{%0,%1,%2,%3}, {%4,%5,%6,%7}, {%8,%9}, {%0,%1,%2,%3};"
                        : "+f"(acc[mi][ni][0]), "+f"(acc[mi][ni][1]),
                          "+f"(acc[mi][ni][2]), "+f"(acc[mi][ni][3])
                        : "r"(af[mi][0]), "r"(af[mi][1]),
                          "r"(af[mi][2]), "r"(af[mi][3]),
                          "r"(bf[ni][0]), "r"(bf[ni][1]));
        }
        __syncthreads();
    }

    #pragma unroll
    for (int mi = 0; mi < 4; mi++) {
        int mrow = mBase + (wm << 6) + (mi << 4) + grp;
        #pragma unroll
        for (int ni = 0; ni < 4; ni++) {
            int nc = nBase + (wn << 5) + (ni << 3) + (tig << 1);
            float b0 = bias1[nc], b1 = bias1[nc + 1];
            if (bias2) { b0 += bias2[nc]; b1 += bias2[nc + 1]; }
            float2 v0 = make_float2(acc[mi][ni][0] + b0, acc[mi][ni][1] + b1);
            float2 v1 = make_float2(acc[mi][ni][2] + b0, acc[mi][ni][3] + b1);
            *(float2*)(C + (size_t)mrow       * N + nc) = v0;
            *(float2*)(C + (size_t)(mrow + 8) * N + nc) = v1;
        }
    }
}

// ---------------- per-timestep LSTM step (wavefront-fused layers) -----------
// Launch l = 0..512. CTAs 0..127: layer0 step t=l (if l<512).
//                    CTAs 128..255: layer1 step t=l-1 (if l>=1).
// Each CTA owns 4 hidden units (16 gate rows). No inter-CTA sync: the stream
// order between launches is the recurrence dependency.
// h buffers are double-buffered by launch parity: writers at launch l write
// buf[l&1]; readers read buf[(l+1)&1] (written at launch l-1).
#define WST 516   // 512 + 4 pad (floats): 16B-aligned rows, conflict-free

__global__ void __launch_bounds__(128)
lstm_step_kernel(int l,
                 const float* __restrict__ Whh0, const float* __restrict__ xg,
                 const float* __restrict__ Whh1, const float* __restrict__ Wih1,
                 const float* __restrict__ bi1,  const float* __restrict__ bh1,
                 float* __restrict__ hs1)
{
    extern __shared__ float sm[];
    int tid  = threadIdx.x;
    bool isL1 = blockIdx.x >= 128;
    int cta  = isL1 ? blockIdx.x - 128 : blockIdx.x;
    int base = cta << 2;                 // first owned hidden unit
    int rp   = (l + 1) & 1;              // read parity
    int wpar = l & 1;                    // write parity

    int g = tid >> 5;                    // gate 0..3
    int u = (tid >> 3) & 3;              // local unit 0..3
    int b = tid & 7;                     // batch 0..7
    int row = (g << 2) + u;              // local gate row 0..15
    int n   = base + u;                  // global hidden unit

    if (!isL1) {
        if (l >= T_SEQ) return;
        int t = l;
        float* Ws = sm;                  // 16 x WST
        float* Hs = sm + 16 * WST;       //  8 x WST (h0_prev, [b][k])
        float* Gs = Hs + 8 * WST;        // 128 gate pre-activations

        // stage W_hh0 slice (16 rows x 512)
        for (int i = tid; i < 2048; i += 128) {   // float4 slots
            int r  = i >> 7, k4 = (i & 127) << 2;
            int gg = r >> 2, uu = r & 3;
            float4 v = *(const float4*)(Whh0 +
                        (size_t)((gg << 9) + base + uu) * HID + k4);
            *(float4*)(Ws + r * WST + k4) = v;
        }
        // stage h0_{t-1} transposed: global [k][b] -> smem [b][k]
        const float* hsrc = g_h0[rp];
        for (int i = tid; i < HID * BATCH; i += 128) {
            int k = i >> 3, bb = i & 7;
            Hs[bb * WST + k] = hsrc[i];
        }
        float xv = __ldg(xg + (size_t)((b << 9) + t) * G4H + (g << 9) + n);
        __syncthreads();

        const float4* wp4 = (const float4*)(Ws + row * WST);
        const float4* hp4 = (const float4*)(Hs + b   * WST);
        float a0 = 0.f, a1 = 0.f, a2 = 0.f, a3 = 0.f;
        #pragma unroll 16
        for (int kc = 0; kc < 128; kc++) {
            float4 w = wp4[kc], h = hp4[kc];
            a0 = fmaf(w.x, h.x, a0); a1 = fmaf(w.y, h.y, a1);
            a2 = fmaf(w.z, h.z, a2); a3 = fmaf(w.w, h.w, a3);
        }
        Gs[tid] = (a0 + a1) + (a2 + a3) + xv;
        __syncthreads();

        if (tid < 32) {
            int uu = tid >> 3, bb = tid & 7;
            int nn = base + uu;
            int id = (uu << 3) + bb;
            float iv = Gs[id], fv = Gs[32 + id];
            float gv = Gs[64 + id], ov = Gs[96 + id];
            float i_ = 1.f / (1.f + expf(-iv));
            float f_ = 1.f / (1.f + expf(-fv));
            float gg = tanhf(gv);
            float o_ = 1.f / (1.f + expf(-ov));
            float c  = f_ * g_c[0][(nn << 3) + bb] + i_ * gg;
            g_c[0][(nn << 3) + bb] = c;
            g_h0[wpar][(nn << 3) + bb] = o_ * tanhf(c);
        }
    } else {
        if (l < 1) return;
        int t = l - 1;
        float* Wh = sm;                   // 16 x WST  (W_hh1 slice)
        float* Wi = sm + 16 * WST;        // 16 x WST  (W_ih1 slice)
        float* H1 = sm + 32 * WST;        //  8 x WST  (h1_prev)
        float* H0 = H1 + 8 * WST;         //  8 x WST  (h0_t = layer input)
        float* Gs = H0 + 8 * WST;         // 128

        // stage both weight slices
        for (int i = tid; i < 4096; i += 128) {
            int half = i >> 11;
            int j  = i & 2047;
            int r  = j >> 7, k4 = (j & 127) << 2;
            int gg = r >> 2, uu = r & 3;
            const float* src = half ? Wih1 : Whh1;
            float4 v = *(const float4*)(src +
                        (size_t)((gg << 9) + base + uu) * HID + k4);
            *(float4*)((half ? Wi : Wh) + r * WST + k4) = v;
        }
        // stage h1_{t-1} and h0_t transposed
        const float* h1src = g_h1[rp];
        const float* h0src = g_h0[rp];    // h0_t written at launch l-1
        for (int i = tid; i < 2 * HID * BATCH; i += 128) {
            int half = i >> 12;
            int j = i & 4095;
            int k = j >> 3, bb = j & 7;
            float v = half ? h0src[j] : h1src[j];
            (half ? H0 : H1)[bb * WST + k] = v;
        }
        float bias = __ldg(bi1 + (g << 9) + n) + __ldg(bh1 + (g << 9) + n);
        __syncthreads();

        const float4* wh4 = (const float4*)(Wh + row * WST);
        const float4* wi4 = (const float4*)(Wi + row * WST);
        const float4* h14 = (const float4*)(H1 + b   * WST);
        const float4* h04 = (const float4*)(H0 + b   * WST);
        float a0 = 0.f, a1 = 0.f, a2 = 0.f, a3 = 0.f;
        #pragma unroll 8
        for (int kc = 0; kc < 128; kc++) {
            float4 w = wh4[kc], h = h14[kc];
            a0 = fmaf(w.x, h.x, a0); a1 = fmaf(w.y, h.y, a1);
            a2 = fmaf(w.z, h.z, a2); a3 = fmaf(w.w, h.w, a3);
            float4 w2 = wi4[kc], h2 = h04[kc];
            a0 = fmaf(w2.x, h2.x, a0); a1 = fmaf(w2.y, h2.y, a1);
            a2 = fmaf(w2.z, h2.z, a2); a3 = fmaf(w2.w, h2.w, a3);
        }
        Gs[tid] = (a0 + a1) + (a2 + a3) + bias;
        __syncthreads();

        if (tid < 32) {
            int uu = tid >> 3, bb = tid & 7;
            int nn = base + uu;
            int id = (uu << 3) + bb;
            float iv = Gs[id], fv = Gs[32 + id];
            float gv = Gs[64 + id], ov = Gs[96 + id];
            float i_ = 1.f / (1.f + expf(-iv));
            float f_ = 1.f / (1.f + expf(-fv));
            float gg = tanhf(gv);
            float o_ = 1.f / (1.f + expf(-ov));
            float c  = f_ * g_c[1][(nn << 3) + bb] + i_ * gg;
            g_c[1][(nn << 3) + bb] = c;
            float h  = o_ * tanhf(c);
            g_h1[wpar][(nn << 3) + bb] = h;
            hs1[(size_t)((bb << 9) + t) * HID + nn] = h;
        }
    }
}

// ---------------- launch -----------------------------------------------------
extern "C" void kernel_launch(void* const* d_in, const int* in_sizes, int n_in,
                              void* d_out, int out_size)
{
    (void)in_sizes; (void)n_in; (void)out_size;
    const int*   ids   = (const int*)d_in[0];
    const float* emb   = (const float*)d_in[1];
    const float* W_ih0 = (const float*)d_in[2];
    const float* W_hh0 = (const float*)d_in[3];
    const float* b_ih0 = (const float*)d_in[4];
    const float* b_hh0 = (const float*)d_in[5];
    const float* W_ih1 = (const float*)d_in[6];
    const float* W_hh1 = (const float*)d_in[7];
    const float* b_ih1 = (const float*)d_in[8];
    const float* b_hh1 = (const float*)d_in[9];
    const float* W_fc  = (const float*)d_in[10];
    const float* b_fc  = (const float*)d_in[11];
    float* out = (float*)d_out;

    float *x0, *xgp, *hs1;
    cudaGetSymbolAddress((void**)&x0,  g_x0);
    cudaGetSymbolAddress((void**)&xgp, g_xg);
    cudaGetSymbolAddress((void**)&hs1, g_hs1);

    // dynamic smem: layer1 branch uses (32 + 16) * WST + 128 floats
    const int step_smem = (48 * WST + 128) * (int)sizeof(float);   // 99,584 B
    cudaFuncSetAttribute(lstm_step_kernel,
                         cudaFuncAttributeMaxDynamicSharedMemorySize, step_smem);

    // 1) gather embeddings
    gather_kernel<<<M_TOT, EMB / 4>>>(ids, emb);

    // 2) xg = x0 @ W_ih0^T + b_ih0 + b_hh0     [4096 x 2048], K=256
    gemm_tf32_kernel<<<dim3(G4H / 128, M_TOT / 128), 256>>>(
        x0, W_ih0, b_ih0, b_hh0, xgp, M_TOT, G4H, EMB);

    // 3) zero h/c state
    reset_kernel<<<(HID * BATCH + 255) / 256, 256>>>();

    // 4) recurrence: one launch per wavefront step
    for (int l = 0; l <= T_SEQ; l++) {
        lstm_step_kernel<<<256, 128, step_smem>>>(
            l, W_hh0, xgp, W_hh1, W_ih1, b_ih1, b_hh1, hs1);
    }

    // 5) logits = hs1 @ W_fc^T + b_fc          [4096 x 32000], K=512
    gemm_tf32_kernel<<<dim3(VOCAB / 128, M_TOT / 128), 256>>>(
        hs1, W_fc, b_fc, nullptr, out, M_TOT, VOCAB, HID);
}